// round 7
// baseline (speedup 1.0000x reference)
#include <cuda_runtime.h>
#include <cuda_bf16.h>
#include <math.h>
#include <stdint.h>

#define BB 64
#define SS 128
#define HH 1024
#define EE 1024
#define EMBD 512
#define VV 32000
#define TT 50
#define G4 4096
#define NPRED (64*50*32000)

typedef unsigned long long ull;

// ---------------- device scratch (static, no runtime alloc) ----------------
__device__ __align__(16) float g_h[BB*HH];
__device__ __align__(16) float g_c[BB*HH];
__device__ __align__(16) float g_prev[BB*EMBD];
__device__ __align__(16) float g_ct[BB*EE];
__device__ __align__(16) float g_gpart[4*BB*G4];
__device__ __align__(16) float g_qpart[8*BB*EE];
__device__ __align__(16) float g_dpart[8*BB*EMBD];
__device__ ull g_amax[BB];
// bf16 plane splits
__device__ __align__(16) __nv_bfloat16 g_a0[BB*EMBD];
__device__ __align__(16) __nv_bfloat16 g_a1[BB*EMBD];
__device__ __align__(16) __nv_bfloat16 g_a2[BB*EMBD];
__device__ __align__(16) __nv_bfloat16 g_w0[(size_t)VV*EMBD];
__device__ __align__(16) __nv_bfloat16 g_w1[(size_t)VV*EMBD];
__device__ __align__(16) __nv_bfloat16 g_w2[(size_t)VV*EMBD];

// ---------------- generic helpers ----------------
__device__ __forceinline__ float sigmoidf_(float x){ return 1.f/(1.f+expf(-x)); }
__device__ __forceinline__ ull packmax(float v, int n){
  unsigned int b = __float_as_uint(v);
  b = (b & 0x80000000u) ? ~b : (b | 0x80000000u);
  return ((ull)b << 32) | (unsigned int)(0x7FFFFFFF - n);
}
__device__ __forceinline__ void ffma2(ull &d, ull a, ull b){
  asm("fma.rn.f32x2 %0, %1, %2, %0;" : "+l"(d) : "l"(a), "l"(b));
}
__device__ __forceinline__ ull pk2(float x){
  ull r; asm("mov.b64 %0, {%1, %1};" : "=l"(r) : "f"(x)); return r;
}
__device__ __forceinline__ float2 unpk(ull v){
  float2 r; asm("mov.b64 {%0, %1}, %2;" : "=f"(r.x), "=f"(r.y) : "l"(v)); return r;
}
__device__ __forceinline__ uint32_t smem_u32(const void* p){
  uint32_t a; asm("{ .reg .u64 t; cvta.to.shared.u64 t, %1; cvt.u32.u64 %0, t; }" : "=r"(a) : "l"(p));
  return a;
}
// mma.sync bf16 (sm_80+, works on plain sm_103 target)
__device__ __forceinline__ void mma16816(float c[4], const uint32_t a[4], const uint32_t b[2]){
  asm volatile("mma.sync.aligned.m16n8k16.row.col.f32.bf16.bf16.f32 "
    "{%0,%1,%2,%3}, {%4,%5,%6,%7}, {%8,%9}, {%0,%1,%2,%3};"
    : "+f"(c[0]), "+f"(c[1]), "+f"(c[2]), "+f"(c[3])
    : "r"(a[0]), "r"(a[1]), "r"(a[2]), "r"(a[3]), "r"(b[0]), "r"(b[1]));
}
__device__ __forceinline__ void ldsm4(uint32_t r[4], uint32_t addr){
  asm volatile("ldmatrix.sync.aligned.m8n8.x4.shared.b16 {%0,%1,%2,%3}, [%4];"
    : "=r"(r[0]), "=r"(r[1]), "=r"(r[2]), "=r"(r[3]) : "r"(addr));
}
__device__ __forceinline__ void cpa16(uint32_t dst, const void* src){
  asm volatile("cp.async.cg.shared.global [%0], [%1], 16;" :: "r"(dst), "l"(src));
}
#define CP_COMMIT() asm volatile("cp.async.commit_group;" ::: "memory")
#define CP_WAIT(n)  asm volatile("cp.async.wait_group %0;" :: "n"(n) : "memory")

// ---------------- FFMA2 GEMM machinery (gates/q/dec) ----------------
struct ALd {
  const float *s0, *s1; int ld0, ld1, cut, tid; float4 v;
  __device__ __forceinline__ void ldg(int k){
    int r = tid >> 2, q = tid & 3;
    const float* s; int ld, kk;
    if (k < cut){ s = s0; ld = ld0; kk = k; } else { s = s1; ld = ld1; kk = k - cut; }
    v = *reinterpret_cast<const float4*>(s + (size_t)r*ld + kk + 4*q);
  }
  __device__ __forceinline__ void sts(float* As) const {
    int r = tid >> 2, q = tid & 3;
    As[(4*q+0)*68+r] = v.x; As[(4*q+1)*68+r] = v.y;
    As[(4*q+2)*68+r] = v.z; As[(4*q+3)*68+r] = v.w;
  }
};
struct BLdT {
  const float *s0, *s1; int ld0, ld1, cut, tid; float4 v0, v1;
  __device__ __forceinline__ void ldg(int k){
    int n = tid >> 1, q = tid & 1;
    const float* s; int ld, kk;
    if (k < cut){ s = s0; ld = ld0; kk = k; } else { s = s1; ld = ld1; kk = k - cut; }
    const float* p = s + (size_t)n*ld + kk + 8*q;
    v0 = *reinterpret_cast<const float4*>(p);
    v1 = *reinterpret_cast<const float4*>(p+4);
  }
  __device__ __forceinline__ void sts(float* Bs) const {
    int n = tid >> 1, kb = (tid & 1)*8;
    Bs[(kb+0)*132+n]=v0.x; Bs[(kb+1)*132+n]=v0.y; Bs[(kb+2)*132+n]=v0.z; Bs[(kb+3)*132+n]=v0.w;
    Bs[(kb+4)*132+n]=v1.x; Bs[(kb+5)*132+n]=v1.y; Bs[(kb+6)*132+n]=v1.z; Bs[(kb+7)*132+n]=v1.w;
  }
};
struct BLdD {
  const float* s; int ldn, tid; float4 v0, v1;
  __device__ __forceinline__ void ldg(int k){
    int kk = tid >> 4, nq = tid & 15;
    const float* p = s + (size_t)(k+kk)*ldn + 8*nq;
    v0 = *reinterpret_cast<const float4*>(p);
    v1 = *reinterpret_cast<const float4*>(p+4);
  }
  __device__ __forceinline__ void sts(float* Bs) const {
    int kk = tid >> 4, nq = tid & 15;
    *reinterpret_cast<float4*>(&Bs[kk*132 + 8*nq])   = v0;
    *reinterpret_cast<float4*>(&Bs[kk*132 + 8*nq+4]) = v1;
  }
};
template<class AL, class BL>
__device__ __forceinline__ void gemm_run(AL a, BL b, int kbase, int ntiles,
                                         ull accv[4][4], int tx, int ty){
  __shared__ __align__(16) float As[2][16*68];
  __shared__ __align__(16) float Bs[2][16*132];
  a.ldg(kbase); b.ldg(kbase);
  a.sts(As[0]); b.sts(Bs[0]);
  __syncthreads();
  int cur = 0;
  for (int kt = 0; kt < ntiles; ++kt){
    bool more = (kt+1) < ntiles;
    if (more){ a.ldg(kbase + (kt+1)*16); b.ldg(kbase + (kt+1)*16); }
    const float* Ac = As[cur]; const float* Bc = Bs[cur];
#pragma unroll
    for (int kk = 0; kk < 16; ++kk){
      const longlong2* ap = reinterpret_cast<const longlong2*>(&Ac[kk*68 + 8*ty]);
      longlong2 aA = ap[0], aB = ap[1];
      float4 bf = *reinterpret_cast<const float4*>(&Bc[kk*132 + 4*tx]);
      ull av[4] = {(ull)aA.x, (ull)aA.y, (ull)aB.x, (ull)aB.y};
      ull bv[4] = {pk2(bf.x), pk2(bf.y), pk2(bf.z), pk2(bf.w)};
#pragma unroll
      for (int i2 = 0; i2 < 4; ++i2)
#pragma unroll
        for (int j = 0; j < 4; ++j)
          ffma2(accv[i2][j], av[i2], bv[j]);
    }
    if (more){ a.sts(As[cur^1]); b.sts(Bs[cur^1]); __syncthreads(); cur ^= 1; }
  }
}
__device__ __forceinline__ void unpack_acc(const ull accv[4][4], float c[8][4]){
#pragma unroll
  for (int i2 = 0; i2 < 4; ++i2){
    float2 u0 = unpk(accv[i2][0]), u1 = unpk(accv[i2][1]);
    float2 u2 = unpk(accv[i2][2]), u3 = unpk(accv[i2][3]);
    c[2*i2  ][0]=u0.x; c[2*i2  ][1]=u1.x; c[2*i2  ][2]=u2.x; c[2*i2  ][3]=u3.x;
    c[2*i2+1][0]=u0.y; c[2*i2+1][1]=u1.y; c[2*i2+1][2]=u2.y; c[2*i2+1][3]=u3.y;
  }
}

// ---------------- init ----------------
__global__ void k_init(const float* __restrict__ ds){
  int idx = blockIdx.x*blockDim.x + threadIdx.x;
  g_h[idx] = ds[idx];
  g_c[idx] = ds[65536 + idx];
  if (idx < BB*EMBD) g_prev[idx] = 0.f;
}

// ---------------- Wv -> 3 bf16 planes (runs once per launch) ----------------
__global__ void k_wsplit(const float* __restrict__ Wv){
  size_t i = ((size_t)blockIdx.x*blockDim.x + threadIdx.x)*4;
  float4 w = *reinterpret_cast<const float4*>(Wv + i);
  float wv[4] = {w.x, w.y, w.z, w.w};
#pragma unroll
  for (int j = 0; j < 4; ++j){
    float x = wv[j];
    __nv_bfloat16 b0 = __float2bfloat16(x); float r1 = x - __bfloat162float(b0);
    __nv_bfloat16 b1 = __float2bfloat16(r1); float r2 = r1 - __bfloat162float(b1);
    __nv_bfloat16 b2 = __float2bfloat16(r2);
    g_w0[i+j] = b0; g_w1[i+j] = b1; g_w2[i+j] = b2;
  }
}

// ---------------- gates ----------------
__global__ void __launch_bounds__(256) k_gates(const float* __restrict__ Wih,
                                               const float* __restrict__ Whh){
  int tid = threadIdx.x, tx = tid & 31, ty = tid >> 5;
  int n0 = blockIdx.x*128, part = blockIdx.y;
  ull accv[4][4] = {};
  ALd  a{g_prev, g_h, 512, 1024, 512, tid, {}};
  BLdT b{Wih + (size_t)n0*512, Whh + (size_t)n0*1024, 512, 1024, 512, tid, {}, {}};
  gemm_run(a, b, part*384, 24, accv, tx, ty);
  float c[8][4]; unpack_acc(accv, c);
  float* o = g_gpart + (size_t)part*BB*G4;
#pragma unroll
  for (int i = 0; i < 8; ++i)
    *reinterpret_cast<float4*>(o + (size_t)(8*ty+i)*G4 + n0 + 4*tx) =
      make_float4(c[i][0], c[i][1], c[i][2], c[i][3]);
}

// ---------------- LSTM elementwise; resets amax ----------------
__global__ void k_lstm(const float* __restrict__ bl){
  int idx = blockIdx.x*blockDim.x + threadIdx.x;
  int m = idx >> 10, j = idx & 1023;
  float gi = bl[j], gf = bl[1024+j], gg = bl[2048+j], go = bl[3072+j];
#pragma unroll
  for (int p = 0; p < 4; ++p){
    const float* gp = g_gpart + (size_t)p*BB*G4 + (size_t)m*G4 + j;
    gi += gp[0]; gf += gp[1024]; gg += gp[2048]; go += gp[3072];
  }
  float c = g_c[idx];
  float cn = sigmoidf_(gf)*c + sigmoidf_(gi)*tanhf(gg);
  g_c[idx] = cn;
  g_h[idx] = sigmoidf_(go)*tanhf(cn);
  if (blockIdx.x == 0 && threadIdx.x < BB) g_amax[threadIdx.x] = 0ull;
}

// ---------------- q = h @ W_attproj ----------------
__global__ void __launch_bounds__(256) k_q(const float* __restrict__ Wap){
  int tid = threadIdx.x, tx = tid & 31, ty = tid >> 5;
  int n0 = blockIdx.x*128, part = blockIdx.y;
  ull accv[4][4] = {};
  ALd  a{g_h, g_h, 1024, 1024, 1<<30, tid, {}};
  BLdD b{Wap + n0, 1024, tid, {}, {}};
  gemm_run(a, b, part*128, 8, accv, tx, ty);
  float c[8][4]; unpack_acc(accv, c);
  float* o = g_qpart + (size_t)part*BB*EE;
#pragma unroll
  for (int i = 0; i < 8; ++i)
    *reinterpret_cast<float4*>(o + (size_t)(8*ty+i)*EE + n0 + 4*tx) =
      make_float4(c[i][0], c[i][1], c[i][2], c[i][3]);
}

// ---------------- fused attention ----------------
__global__ void k_attn(const float* __restrict__ enc, const int* __restrict__ enc_len){
  __shared__ float qv[1024];
  __shared__ float sc[128];
  __shared__ float sr[128];
  int tid = threadIdx.x, b = blockIdx.x;
  for (int e = tid; e < 1024; e += 512){
    float s = 0.f;
#pragma unroll
    for (int p = 0; p < 8; ++p) s += g_qpart[(size_t)p*BB*EE + (size_t)b*EE + e];
    qv[e] = s;
  }
  __syncthreads();
  const float* eb = enc + (size_t)b*SS*EE;
  int w = tid >> 5, lane = tid & 31;
  for (int s = w; s < 128; s += 16){
    const float* er = eb + (size_t)s*EE;
    float acc = 0.f;
    for (int e = lane; e < 1024; e += 32) acc = fmaf(er[e], qv[e], acc);
#pragma unroll
    for (int o = 16; o; o >>= 1) acc += __shfl_xor_sync(0xffffffffu, acc, o);
    if (lane == 0) sc[s] = acc;
  }
  __syncthreads();
  int len = enc_len[b];
  bool act = tid < 128;
  float v = -1e9f;
  if (act){ v = (tid < len) ? sc[tid] : -1e9f; sr[tid] = v; }
  __syncthreads();
  for (int o = 64; o; o >>= 1){ if (tid < o) sr[tid] = fmaxf(sr[tid], sr[tid+o]); __syncthreads(); }
  float mx = sr[0]; __syncthreads();
  float ev = 0.f;
  if (act){ ev = expf(v - mx); sr[tid] = ev; }
  __syncthreads();
  for (int o = 64; o; o >>= 1){ if (tid < o) sr[tid] += sr[tid+o]; __syncthreads(); }
  float inv = 1.f / sr[0];
  __syncthreads();
  if (act) sc[tid] = ev * inv;
  __syncthreads();
  float a0 = 0.f, a1 = 0.f;
  for (int s = 0; s < 128; ++s){
    float al = sc[s];
    const float* er = eb + (size_t)s*EE;
    a0 = fmaf(al, er[tid      ], a0);
    a1 = fmaf(al, er[tid + 512], a1);
  }
  float* ct = g_ct + (size_t)b*EE;
  ct[tid] = a0; ct[tid+512] = a1;
}

// ---------------- dec = [h | c_t] @ W_out^T ----------------
__global__ void __launch_bounds__(256) k_dec(const float* __restrict__ Wout){
  int tid = threadIdx.x, tx = tid & 31, ty = tid >> 5;
  int n0 = blockIdx.x*128, part = blockIdx.y;
  ull accv[4][4] = {};
  ALd  a{g_h, g_ct, 1024, 1024, 1024, tid, {}};
  BLdT b{Wout + (size_t)n0*2048, Wout + (size_t)n0*2048, 2048, 2048, 1<<30, tid, {}, {}};
  gemm_run(a, b, part*256, 16, accv, tx, ty);
  float c[8][4]; unpack_acc(accv, c);
  float* o = g_dpart + (size_t)part*BB*EMBD;
#pragma unroll
  for (int i = 0; i < 8; ++i)
    *reinterpret_cast<float4*>(o + (size_t)(8*ty+i)*EMBD + n0 + 4*tx) =
      make_float4(c[i][0], c[i][1], c[i][2], c[i][3]);
}

// ---------------- sum dec parts -> bf16 plane split ----------------
__global__ void k_dsplit(){
  int i = blockIdx.x*blockDim.x + threadIdx.x;   // 32768
  float s = 0.f;
#pragma unroll
  for (int p = 0; p < 8; ++p) s += g_dpart[p*BB*EMBD + i];
  __nv_bfloat16 a0 = __float2bfloat16(s); float r1 = s - __bfloat162float(a0);
  __nv_bfloat16 a1 = __float2bfloat16(r1); float r2 = r1 - __bfloat162float(a1);
  __nv_bfloat16 a2 = __float2bfloat16(r2);
  g_a0[i] = a0; g_a1[i] = a1; g_a2[i] = a2;
}

// ---------------- vocab via mma.sync bf16, 3-plane compensated ----------------
// Block: M=64 x N=256, K chunks of 32, cp.async double buffer.
// SMEM buffer layout (per buffer, rows padded to 80B):
//   A region: 192 rows (plane*64 + m), 64B data each       -> 15360 B
//   B region: 768 rows (plane*256 + n), 64B data each      -> 61440 B
#define VBOFF 15360
#define VBUFSZ 76800
#define VSMEM (2*VBUFSZ + 512)

__global__ void __launch_bounds__(256) k_vocab_mma(float* __restrict__ out, int t){
  extern __shared__ __align__(128) char smem[];
  uint32_t sb = smem_u32(smem);
  int tid = threadIdx.x, wid = tid >> 5, lane = tid & 31;
  int n0 = blockIdx.x * 256;
  int wm = wid >> 2, wn = wid & 3;     // warp tile: rows 32*wm, cols 64*wn
  ull* sred = (ull*)(smem + 2*VBUFSZ);
  if (tid < 64) sred[tid] = 0ull;

  const __nv_bfloat16* a_pl[3] = {g_a0, g_a1, g_a2};
  const __nv_bfloat16* b_pl[3] = {g_w0 + (size_t)n0*EMBD, g_w1 + (size_t)n0*EMBD,
                                  g_w2 + (size_t)n0*EMBD};

  float acc[2][8][4];
#pragma unroll
  for (int mi = 0; mi < 2; ++mi)
#pragma unroll
    for (int ni = 0; ni < 8; ++ni)
#pragma unroll
      for (int e = 0; e < 4; ++e) acc[mi][ni][e] = 0.f;

  // --- async load of one K=32 chunk into buffer (c&1) ---
  auto issue = [&](int c){
    uint32_t bb = sb + (uint32_t)(c & 1)*VBUFSZ;
    int kc = c*32;
#pragma unroll
    for (int it = 0; it < 15; ++it){
      int i = it*256 + tid;
      if (i < 768){
        int row = i >> 2, g = i & 3;
        int p = row >> 6, m = row & 63;
        cpa16(bb + (uint32_t)row*80 + g*16, a_pl[p] + (size_t)m*EMBD + kc + g*8);
      } else {
        int j = i - 768, row = j >> 2, g = j & 3;
        int p = row >> 8, n = row & 255;
        cpa16(bb + VBOFF + (uint32_t)row*80 + g*16, b_pl[p] + (size_t)n*EMBD + kc + g*8);
      }
    }
    CP_COMMIT();
  };

  // lane address components for ldmatrix
  int lm  = lane & 15;                      // A: row within m16
  int kbA = ((lane >> 4) & 1) * 16;         // A: lanes 16-31 -> k+8 (16B)
  int ln  = (lane & 7) | ((lane >> 1) & 8); // B: lanes 16-31 -> n+8
  int kbB = ((lane >> 3) & 1) * 16;         // B: lanes 8-15,24-31 -> k+8

  issue(0);
  for (int c = 0; c < 16; ++c){
    if (c + 1 < 16){ issue(c + 1); CP_WAIT(1); } else { CP_WAIT(0); }
    __syncthreads();
    uint32_t bb = sb + (uint32_t)(c & 1)*VBUFSZ;
#pragma unroll
    for (int kk = 0; kk < 2; ++kk){
      uint32_t aF[3][2][4];
#pragma unroll
      for (int p = 0; p < 3; ++p)
#pragma unroll
        for (int mi = 0; mi < 2; ++mi)
          ldsm4(aF[p][mi], bb + (uint32_t)(p*64 + wm*32 + mi*16 + lm)*80 + kk*32 + kbA);
#pragma unroll
      for (int pb = 0; pb < 3; ++pb){
        uint32_t bF[8][2];
#pragma unroll
        for (int g = 0; g < 4; ++g){
          uint32_t r[4];
          ldsm4(r, bb + VBOFF + (uint32_t)(pb*256 + wn*64 + g*16 + ln)*80 + kk*32 + kbB);
          bF[2*g][0] = r[0]; bF[2*g][1] = r[1];
          bF[2*g+1][0] = r[2]; bF[2*g+1][1] = r[3];
        }
        int npa = (pb == 0) ? 3 : (pb == 1) ? 2 : 1;  // products with i+j<=2
#pragma unroll
        for (int pa = 0; pa < 3; ++pa){
          if (pa >= npa) break;
#pragma unroll
          for (int mi = 0; mi < 2; ++mi)
#pragma unroll
            for (int ni = 0; ni < 8; ++ni)
              mma16816(acc[mi][ni], aF[pa][mi], bF[ni]);
        }
      }
    }
    __syncthreads();
  }

  // --- epilogue: store logits (full 32B sectors) + argmax ---
  int r4 = lane >> 2, c2 = (lane & 3)*2;
#pragma unroll
  for (int mi = 0; mi < 2; ++mi)
#pragma unroll
    for (int h = 0; h < 2; ++h){
      int m = wm*32 + mi*16 + r4 + 8*h;
      float* orow = out + ((size_t)m*TT + t)*VV + n0 + wn*64;
      ull best = 0ull;
#pragma unroll
      for (int ni = 0; ni < 8; ++ni){
        float v0 = acc[mi][ni][2*h], v1 = acc[mi][ni][2*h+1];
        int cn = n0 + wn*64 + ni*8 + c2;
        ull p0 = packmax(v0, cn), p1 = packmax(v1, cn+1);
        if (p1 > p0) p0 = p1;
        if (p0 > best) best = p0;
        __stcs(reinterpret_cast<float2*>(orow + ni*8 + c2), make_float2(v0, v1));
      }
      ull o1 = __shfl_xor_sync(0xffffffffu, best, 1); if (o1 > best) best = o1;
      ull o2 = __shfl_xor_sync(0xffffffffu, best, 2); if (o2 > best) best = o2;
      if ((lane & 3) == 0) atomicMax(&sred[m], best);
    }
  __syncthreads();
  if (tid < 64 && sred[tid]) atomicMax(&g_amax[tid], sred[tid]);
}

// ---------------- greedy symbol -> prev embedding ----------------
__global__ void k_update(const float* __restrict__ emb){
  int b = blockIdx.x;
  unsigned int low = (unsigned int)(g_amax[b] & 0xFFFFFFFFull);
  int sym = 0x7FFFFFFF - (int)low;
  g_prev[(size_t)b*EMBD + threadIdx.x] = emb[(size_t)sym*EMBD + threadIdx.x];
}

// ---------------- in-place log-softmax over V ----------------
__global__ void k_lsm(float* __restrict__ out){
  __shared__ float sr[256];
  float* p = out + (size_t)blockIdx.x * VV;
  int tid = threadIdx.x;
  float mx = -3.4e38f;
  for (int i = tid; i < VV; i += 256) mx = fmaxf(mx, __ldcs(p+i));
  sr[tid] = mx; __syncthreads();
  for (int o = 128; o; o >>= 1){ if (tid < o) sr[tid] = fmaxf(sr[tid], sr[tid+o]); __syncthreads(); }
  mx = sr[0]; __syncthreads();
  float s = 0.f;
  for (int i = tid; i < VV; i += 256) s += expf(__ldcs(p+i) - mx);
  sr[tid] = s; __syncthreads();
  for (int o = 128; o; o >>= 1){ if (tid < o) sr[tid] += sr[tid+o]; __syncthreads(); }
  float shift = mx + logf(sr[0]);
  __syncthreads();
  for (int i = tid; i < VV; i += 256) __stcs(p+i, __ldcs(p+i) - shift);
}

__global__ void k_tail(float* __restrict__ out){ out[NPRED + threadIdx.x] = 50.0f; }

extern "C" void kernel_launch(void* const* d_in, const int* in_sizes, int n_in,
                              void* d_out, int out_size){
  const float* ds   = (const float*)d_in[0];
  const float* enc  = (const float*)d_in[1];
  const int*   elen = (const int*)  d_in[2];
  const float* Wih  = (const float*)d_in[4];
  const float* Whh  = (const float*)d_in[5];
  const float* bl   = (const float*)d_in[6];
  const float* Wap  = (const float*)d_in[7];
  const float* Wout = (const float*)d_in[8];
  const float* Wv   = (const float*)d_in[9];
  const float* emb  = (const float*)d_in[10];
  float* out = (float*)d_out;

  cudaFuncSetAttribute(k_vocab_mma, cudaFuncAttributeMaxDynamicSharedMemorySize, VSMEM);

  k_init<<<256,256>>>(ds);
  k_wsplit<<<16000,256>>>(Wv);
  for (int t = 0; t < TT; ++t){
    k_gates<<<dim3(32,4),256>>>(Wih, Whh);
    k_lstm<<<256,256>>>(bl);
    k_q<<<dim3(8,8),256>>>(Wap);
    k_attn<<<64,512>>>(enc, elen);
    k_dec<<<dim3(4,8),256>>>(Wout);
    k_dsplit<<<128,256>>>();
    k_vocab_mma<<<125,256,VSMEM>>>(out, t);
    k_update<<<64,512>>>(emb);
  }
  k_lsm<<<3200,256>>>(out);
  if (out_size >= NPRED + 64) k_tail<<<1,64>>>(out);
}

// round 8
// speedup vs baseline: 1.3631x; 1.3631x over previous
#include <cuda_runtime.h>
#include <cuda_bf16.h>
#include <math.h>
#include <stdint.h>

#define BB 64
#define SS 128
#define HH 1024
#define EE 1024
#define EMBD 512
#define VV 32000
#define TT 50
#define G4 4096
#define NPRED (64*50*32000)

typedef unsigned long long ull;

// ---------------- device scratch (static, no runtime alloc) ----------------
__device__ __align__(16) float g_h[BB*HH];
__device__ __align__(16) float g_c[BB*HH];
__device__ __align__(16) float g_prev[BB*EMBD];
__device__ __align__(16) float g_ct[BB*EE];
__device__ __align__(16) float g_gpart[4*BB*G4];
__device__ __align__(16) float g_qpart[8*BB*EE];
__device__ __align__(16) float g_dpart[8*BB*EMBD];
__device__ __align__(16) float g_dech[(size_t)TT*BB*EMBD];      // fp32 dec history
__device__ __align__(16) __nv_bfloat16 g_a0[BB*EMBD];           // current-step dec planes
__device__ __align__(16) __nv_bfloat16 g_a1[BB*EMBD];
__device__ __align__(16) __nv_bfloat16 g_ah0[(size_t)TT*BB*EMBD]; // dec history planes
__device__ __align__(16) __nv_bfloat16 g_ah1[(size_t)TT*BB*EMBD];
__device__ __align__(16) __nv_bfloat16 g_w0[(size_t)VV*EMBD];
__device__ __align__(16) __nv_bfloat16 g_w1[(size_t)VV*EMBD];
__device__ __align__(16) __nv_bfloat16 g_l1[(size_t)BB*VV];     // approx logits scratch

// ---------------- generic helpers ----------------
__device__ __forceinline__ float sigmoidf_(float x){ return 1.f/(1.f+expf(-x)); }
__device__ __forceinline__ ull packmax(float v, int n){
  unsigned int b = __float_as_uint(v);
  b = (b & 0x80000000u) ? ~b : (b | 0x80000000u);
  return ((ull)b << 32) | (unsigned int)(0x7FFFFFFF - n);
}
__device__ __forceinline__ void ffma2(ull &d, ull a, ull b){
  asm("fma.rn.f32x2 %0, %1, %2, %0;" : "+l"(d) : "l"(a), "l"(b));
}
__device__ __forceinline__ ull pk2(float x){
  ull r; asm("mov.b64 %0, {%1, %1};" : "=l"(r) : "f"(x)); return r;
}
__device__ __forceinline__ float2 unpk(ull v){
  float2 r; asm("mov.b64 {%0, %1}, %2;" : "=f"(r.x), "=f"(r.y) : "l"(v)); return r;
}
__device__ __forceinline__ uint32_t smem_u32(const void* p){
  uint32_t a; asm("{ .reg .u64 t; cvta.to.shared.u64 t, %1; cvt.u32.u64 %0, t; }" : "=r"(a) : "l"(p));
  return a;
}
__device__ __forceinline__ void mma16816(float c[4], const uint32_t a[4], const uint32_t b[2]){
  asm volatile("mma.sync.aligned.m16n8k16.row.col.f32.bf16.bf16.f32 "
    "{%0,%1,%2,%3}, {%4,%5,%6,%7}, {%8,%9}, {%0,%1,%2,%3};"
    : "+f"(c[0]), "+f"(c[1]), "+f"(c[2]), "+f"(c[3])
    : "r"(a[0]), "r"(a[1]), "r"(a[2]), "r"(a[3]), "r"(b[0]), "r"(b[1]));
}
__device__ __forceinline__ void ldsm4(uint32_t r[4], uint32_t addr){
  asm volatile("ldmatrix.sync.aligned.m8n8.x4.shared.b16 {%0,%1,%2,%3}, [%4];"
    : "=r"(r[0]), "=r"(r[1]), "=r"(r[2]), "=r"(r[3]) : "r"(addr));
}
__device__ __forceinline__ void cpa16(uint32_t dst, const void* src){
  asm volatile("cp.async.cg.shared.global [%0], [%1], 16;" :: "r"(dst), "l"(src));
}
#define CP_COMMIT() asm volatile("cp.async.commit_group;" ::: "memory")
#define CP_WAIT(n)  asm volatile("cp.async.wait_group %0;" :: "n"(n) : "memory")

// ---------------- FFMA2 GEMM machinery (gates/q/dec) ----------------
struct ALd {
  const float *s0, *s1; int ld0, ld1, cut, tid; float4 v;
  __device__ __forceinline__ void ldg(int k){
    int r = tid >> 2, q = tid & 3;
    const float* s; int ld, kk;
    if (k < cut){ s = s0; ld = ld0; kk = k; } else { s = s1; ld = ld1; kk = k - cut; }
    v = *reinterpret_cast<const float4*>(s + (size_t)r*ld + kk + 4*q);
  }
  __device__ __forceinline__ void sts(float* As) const {
    int r = tid >> 2, q = tid & 3;
    As[(4*q+0)*68+r] = v.x; As[(4*q+1)*68+r] = v.y;
    As[(4*q+2)*68+r] = v.z; As[(4*q+3)*68+r] = v.w;
  }
};
struct BLdT {
  const float *s0, *s1; int ld0, ld1, cut, tid; float4 v0, v1;
  __device__ __forceinline__ void ldg(int k){
    int n = tid >> 1, q = tid & 1;
    const float* s; int ld, kk;
    if (k < cut){ s = s0; ld = ld0; kk = k; } else { s = s1; ld = ld1; kk = k - cut; }
    const float* p = s + (size_t)n*ld + kk + 8*q;
    v0 = *reinterpret_cast<const float4*>(p);
    v1 = *reinterpret_cast<const float4*>(p+4);
  }
  __device__ __forceinline__ void sts(float* Bs) const {
    int n = tid >> 1, kb = (tid & 1)*8;
    Bs[(kb+0)*132+n]=v0.x; Bs[(kb+1)*132+n]=v0.y; Bs[(kb+2)*132+n]=v0.z; Bs[(kb+3)*132+n]=v0.w;
    Bs[(kb+4)*132+n]=v1.x; Bs[(kb+5)*132+n]=v1.y; Bs[(kb+6)*132+n]=v1.z; Bs[(kb+7)*132+n]=v1.w;
  }
};
struct BLdD {
  const float* s; int ldn, tid; float4 v0, v1;
  __device__ __forceinline__ void ldg(int k){
    int kk = tid >> 4, nq = tid & 15;
    const float* p = s + (size_t)(k+kk)*ldn + 8*nq;
    v0 = *reinterpret_cast<const float4*>(p);
    v1 = *reinterpret_cast<const float4*>(p+4);
  }
  __device__ __forceinline__ void sts(float* Bs) const {
    int kk = tid >> 4, nq = tid & 15;
    *reinterpret_cast<float4*>(&Bs[kk*132 + 8*nq])   = v0;
    *reinterpret_cast<float4*>(&Bs[kk*132 + 8*nq+4]) = v1;
  }
};
template<class AL, class BL>
__device__ __forceinline__ void gemm_run(AL a, BL b, int kbase, int ntiles,
                                         ull accv[4][4], int tx, int ty){
  __shared__ __align__(16) float As[2][16*68];
  __shared__ __align__(16) float Bs[2][16*132];
  a.ldg(kbase); b.ldg(kbase);
  a.sts(As[0]); b.sts(Bs[0]);
  __syncthreads();
  int cur = 0;
  for (int kt = 0; kt < ntiles; ++kt){
    bool more = (kt+1) < ntiles;
    if (more){ a.ldg(kbase + (kt+1)*16); b.ldg(kbase + (kt+1)*16); }
    const float* Ac = As[cur]; const float* Bc = Bs[cur];
#pragma unroll
    for (int kk = 0; kk < 16; ++kk){
      const longlong2* ap = reinterpret_cast<const longlong2*>(&Ac[kk*68 + 8*ty]);
      longlong2 aA = ap[0], aB = ap[1];
      float4 bf = *reinterpret_cast<const float4*>(&Bc[kk*132 + 4*tx]);
      ull av[4] = {(ull)aA.x, (ull)aA.y, (ull)aB.x, (ull)aB.y};
      ull bv[4] = {pk2(bf.x), pk2(bf.y), pk2(bf.z), pk2(bf.w)};
#pragma unroll
      for (int i2 = 0; i2 < 4; ++i2)
#pragma unroll
        for (int j = 0; j < 4; ++j)
          ffma2(accv[i2][j], av[i2], bv[j]);
    }
    if (more){ a.sts(As[cur^1]); b.sts(Bs[cur^1]); __syncthreads(); cur ^= 1; }
  }
}
__device__ __forceinline__ void unpack_acc(const ull accv[4][4], float c[8][4]){
#pragma unroll
  for (int i2 = 0; i2 < 4; ++i2){
    float2 u0 = unpk(accv[i2][0]), u1 = unpk(accv[i2][1]);
    float2 u2 = unpk(accv[i2][2]), u3 = unpk(accv[i2][3]);
    c[2*i2  ][0]=u0.x; c[2*i2  ][1]=u1.x; c[2*i2  ][2]=u2.x; c[2*i2  ][3]=u3.x;
    c[2*i2+1][0]=u0.y; c[2*i2+1][1]=u1.y; c[2*i2+1][2]=u2.y; c[2*i2+1][3]=u3.y;
  }
}

// ---------------- init ----------------
__global__ void k_init(const float* __restrict__ ds){
  int idx = blockIdx.x*blockDim.x + threadIdx.x;
  g_h[idx] = ds[idx];
  g_c[idx] = ds[65536 + idx];
  if (idx < BB*EMBD) g_prev[idx] = 0.f;
}

// ---------------- Wv -> 2 bf16 planes ----------------
__global__ void k_wsplit(const float* __restrict__ Wv){
  size_t i = ((size_t)blockIdx.x*blockDim.x + threadIdx.x)*4;
  float4 w = *reinterpret_cast<const float4*>(Wv + i);
  float wv[4] = {w.x, w.y, w.z, w.w};
#pragma unroll
  for (int j = 0; j < 4; ++j){
    float x = wv[j];
    __nv_bfloat16 b0 = __float2bfloat16(x); float r1 = x - __bfloat162float(b0);
    __nv_bfloat16 b1 = __float2bfloat16(r1);
    g_w0[i+j] = b0; g_w1[i+j] = b1;
  }
}

// ---------------- gates ----------------
__global__ void __launch_bounds__(256) k_gates(const float* __restrict__ Wih,
                                               const float* __restrict__ Whh){
  int tid = threadIdx.x, tx = tid & 31, ty = tid >> 5;
  int n0 = blockIdx.x*128, part = blockIdx.y;
  ull accv[4][4] = {};
  ALd  a{g_prev, g_h, 512, 1024, 512, tid, {}};
  BLdT b{Wih + (size_t)n0*512, Whh + (size_t)n0*1024, 512, 1024, 512, tid, {}, {}};
  gemm_run(a, b, part*384, 24, accv, tx, ty);
  float c[8][4]; unpack_acc(accv, c);
  float* o = g_gpart + (size_t)part*BB*G4;
#pragma unroll
  for (int i = 0; i < 8; ++i)
    *reinterpret_cast<float4*>(o + (size_t)(8*ty+i)*G4 + n0 + 4*tx) =
      make_float4(c[i][0], c[i][1], c[i][2], c[i][3]);
}

// ---------------- LSTM elementwise ----------------
__global__ void k_lstm(const float* __restrict__ bl){
  int idx = blockIdx.x*blockDim.x + threadIdx.x;
  int m = idx >> 10, j = idx & 1023;
  float gi = bl[j], gf = bl[1024+j], gg = bl[2048+j], go = bl[3072+j];
#pragma unroll
  for (int p = 0; p < 4; ++p){
    const float* gp = g_gpart + (size_t)p*BB*G4 + (size_t)m*G4 + j;
    gi += gp[0]; gf += gp[1024]; gg += gp[2048]; go += gp[3072];
  }
  float c = g_c[idx];
  float cn = sigmoidf_(gf)*c + sigmoidf_(gi)*tanhf(gg);
  g_c[idx] = cn;
  g_h[idx] = sigmoidf_(go)*tanhf(cn);
}

// ---------------- q = h @ W_attproj ----------------
__global__ void __launch_bounds__(256) k_q(const float* __restrict__ Wap){
  int tid = threadIdx.x, tx = tid & 31, ty = tid >> 5;
  int n0 = blockIdx.x*128, part = blockIdx.y;
  ull accv[4][4] = {};
  ALd  a{g_h, g_h, 1024, 1024, 1<<30, tid, {}};
  BLdD b{Wap + n0, 1024, tid, {}, {}};
  gemm_run(a, b, part*128, 8, accv, tx, ty);
  float c[8][4]; unpack_acc(accv, c);
  float* o = g_qpart + (size_t)part*BB*EE;
#pragma unroll
  for (int i = 0; i < 8; ++i)
    *reinterpret_cast<float4*>(o + (size_t)(8*ty+i)*EE + n0 + 4*tx) =
      make_float4(c[i][0], c[i][1], c[i][2], c[i][3]);
}

// ---------------- fused attention (vectorized) ----------------
__global__ void k_attn(const float* __restrict__ enc, const int* __restrict__ enc_len){
  __shared__ __align__(16) float qv[1024];
  __shared__ float sc[128];
  __shared__ float sr[128];
  int tid = threadIdx.x, b = blockIdx.x;
  for (int e = tid; e < 1024; e += 512){
    float s = 0.f;
#pragma unroll
    for (int p = 0; p < 8; ++p) s += g_qpart[(size_t)p*BB*EE + (size_t)b*EE + e];
    qv[e] = s;
  }
  __syncthreads();
  const float* eb = enc + (size_t)b*SS*EE;
  const float4* qv4 = reinterpret_cast<const float4*>(qv);
  int w = tid >> 5, lane = tid & 31;
  for (int s = w; s < 128; s += 16){
    const float4* er4 = reinterpret_cast<const float4*>(eb + (size_t)s*EE);
    float acc = 0.f;
#pragma unroll
    for (int e4 = 0; e4 < 8; ++e4){
      float4 ev = er4[lane + 32*e4], qvv = qv4[lane + 32*e4];
      acc = fmaf(ev.x, qvv.x, acc); acc = fmaf(ev.y, qvv.y, acc);
      acc = fmaf(ev.z, qvv.z, acc); acc = fmaf(ev.w, qvv.w, acc);
    }
#pragma unroll
    for (int o = 16; o; o >>= 1) acc += __shfl_xor_sync(0xffffffffu, acc, o);
    if (lane == 0) sc[s] = acc;
  }
  __syncthreads();
  int len = enc_len[b];
  bool act = tid < 128;
  float v = -1e9f;
  if (act){ v = (tid < len) ? sc[tid] : -1e9f; sr[tid] = v; }
  __syncthreads();
  for (int o = 64; o; o >>= 1){ if (tid < o) sr[tid] = fmaxf(sr[tid], sr[tid+o]); __syncthreads(); }
  float mx = sr[0]; __syncthreads();
  float ev = 0.f;
  if (act){ ev = expf(v - mx); sr[tid] = ev; }
  __syncthreads();
  for (int o = 64; o; o >>= 1){ if (tid < o) sr[tid] += sr[tid+o]; __syncthreads(); }
  float inv = 1.f / sr[0];
  __syncthreads();
  if (act) sc[tid] = ev * inv;
  __syncthreads();
  float2 a01 = make_float2(0.f, 0.f);
  const float2* eb2 = reinterpret_cast<const float2*>(eb);
  for (int s = 0; s < 128; ++s){
    float al = sc[s];
    float2 e2 = eb2[(size_t)s*512 + tid];
    a01.x = fmaf(al, e2.x, a01.x); a01.y = fmaf(al, e2.y, a01.y);
  }
  reinterpret_cast<float2*>(g_ct + (size_t)b*EE)[tid] = a01;
}

// ---------------- dec = [h | c_t] @ W_out^T ----------------
__global__ void __launch_bounds__(256) k_dec(const float* __restrict__ Wout){
  int tid = threadIdx.x, tx = tid & 31, ty = tid >> 5;
  int n0 = blockIdx.x*128, part = blockIdx.y;
  ull accv[4][4] = {};
  ALd  a{g_h, g_ct, 1024, 1024, 1024, tid, {}};
  BLdT b{Wout + (size_t)n0*2048, Wout + (size_t)n0*2048, 2048, 2048, 1<<30, tid, {}, {}};
  gemm_run(a, b, part*256, 16, accv, tx, ty);
  float c[8][4]; unpack_acc(accv, c);
  float* o = g_dpart + (size_t)part*BB*EMBD;
#pragma unroll
  for (int i = 0; i < 8; ++i)
    *reinterpret_cast<float4*>(o + (size_t)(8*ty+i)*EMBD + n0 + 4*tx) =
      make_float4(c[i][0], c[i][1], c[i][2], c[i][3]);
}

// ---------------- sum dec parts -> history + 2 bf16 planes ----------------
__global__ void k_dsplit(int t){
  int i = blockIdx.x*blockDim.x + threadIdx.x;   // 32768
  float s = 0.f;
#pragma unroll
  for (int p = 0; p < 8; ++p) s += g_dpart[p*BB*EMBD + i];
  g_dech[(size_t)t*BB*EMBD + i] = s;
  __nv_bfloat16 a0 = __float2bfloat16(s); float r1 = s - __bfloat162float(a0);
  __nv_bfloat16 a1 = __float2bfloat16(r1);
  g_a0[i] = a0; g_a1[i] = a1;
}

// ---------------- in-loop approx vocab: (a0+a1) x b0 -> bf16 scratch ----------------
// SMEM/buffer: A 128 rows x 80B = 10240; B 256 rows x 80B = 20480; buf 30720 x2
#define VBOFF1 10240
#define VBUF1 30720
#define VSMEM1 (2*VBUF1 + 256)

__global__ void __launch_bounds__(256) k_vocab1(){
  extern __shared__ __align__(128) char smem[];
  uint32_t sb = smem_u32(smem);
  int tid = threadIdx.x, wid = tid >> 5, lane = tid & 31;
  int n0 = blockIdx.x * 256;
  int wm = wid >> 2, wn = wid & 3;

  float acc[2][8][4];
#pragma unroll
  for (int mi = 0; mi < 2; ++mi)
#pragma unroll
    for (int ni = 0; ni < 8; ++ni)
#pragma unroll
      for (int e = 0; e < 4; ++e) acc[mi][ni][e] = 0.f;

  auto issue = [&](int c){
    uint32_t bb = sb + (uint32_t)(c & 1)*VBUF1;
    int kc = c*32;
#pragma unroll
    for (int it = 0; it < 6; ++it){
      int i = it*256 + tid;
      if (i < 512){
        int row = i >> 2, g = i & 3;
        int p = row >> 6, m = row & 63;
        const __nv_bfloat16* src = (p ? g_a1 : g_a0) + (size_t)m*EMBD + kc + g*8;
        cpa16(bb + (uint32_t)row*80 + g*16, src);
      } else {
        int j = i - 512, row = j >> 2, g = j & 3;
        cpa16(bb + VBOFF1 + (uint32_t)row*80 + g*16,
              g_w0 + (size_t)(n0 + row)*EMBD + kc + g*8);
      }
    }
    CP_COMMIT();
  };

  int lm  = lane & 15;
  int kbA = ((lane >> 4) & 1) * 16;
  int ln  = (lane & 7) | ((lane >> 1) & 8);
  int kbB = ((lane >> 3) & 1) * 16;

  issue(0);
  for (int c = 0; c < 16; ++c){
    if (c + 1 < 16){ issue(c + 1); CP_WAIT(1); } else { CP_WAIT(0); }
    __syncthreads();
    uint32_t bb = sb + (uint32_t)(c & 1)*VBUF1;
#pragma unroll
    for (int kk = 0; kk < 2; ++kk){
      uint32_t aF[2][2][4];
#pragma unroll
      for (int p = 0; p < 2; ++p)
#pragma unroll
        for (int mi = 0; mi < 2; ++mi)
          ldsm4(aF[p][mi], bb + (uint32_t)(p*64 + wm*32 + mi*16 + lm)*80 + kk*32 + kbA);
      uint32_t bF[8][2];
#pragma unroll
      for (int g = 0; g < 4; ++g){
        uint32_t r[4];
        ldsm4(r, bb + VBOFF1 + (uint32_t)(wn*64 + g*16 + ln)*80 + kk*32 + kbB);
        bF[2*g][0] = r[0]; bF[2*g][1] = r[1];
        bF[2*g+1][0] = r[2]; bF[2*g+1][1] = r[3];
      }
#pragma unroll
      for (int pa = 0; pa < 2; ++pa)
#pragma unroll
        for (int mi = 0; mi < 2; ++mi)
#pragma unroll
          for (int ni = 0; ni < 8; ++ni)
            mma16816(acc[mi][ni], aF[pa][mi], bF[ni]);
    }
    __syncthreads();
  }

  int r4 = lane >> 2, c2 = (lane & 3)*2;
#pragma unroll
  for (int mi = 0; mi < 2; ++mi)
#pragma unroll
    for (int h = 0; h < 2; ++h){
      int m = wm*32 + mi*16 + r4 + 8*h;
      __nv_bfloat16* orow = g_l1 + (size_t)m*VV + n0 + wn*64;
#pragma unroll
      for (int ni = 0; ni < 8; ++ni){
        __nv_bfloat162 y = __floats2bfloat162_rn(acc[mi][ni][2*h], acc[mi][ni][2*h+1]);
        *reinterpret_cast<__nv_bfloat162*>(orow + ni*8 + c2) = y;
      }
    }
}

// ---------------- candidate refine + exact argmax + embedding gather ----------------
__global__ void k_refine(const float* __restrict__ Wv, const float* __restrict__ emb, int t){
  __shared__ float sm[256], ss[256], sq[256];
  __shared__ float dsh[512];
  __shared__ int cand[64];
  __shared__ int ccnt;
  __shared__ ull bestsh;
  int b = blockIdx.x, tid = threadIdx.x;
  const __nv_bfloat16* row = g_l1 + (size_t)b*VV;
  const float* dsrc = g_dech + (size_t)t*BB*EMBD + (size_t)b*EMBD;
  dsh[tid] = dsrc[tid]; dsh[tid+256] = dsrc[tid+256];
  if (tid == 0){ ccnt = 0; bestsh = 0ull; }
  float mx = -3.4e38f, sum = 0.f, ssq = 0.f;
  for (int i = tid; i < VV; i += 256){
    float v = __bfloat162float(row[i]);
    mx = fmaxf(mx, v); sum += v; ssq = fmaf(v, v, ssq);
  }
  sm[tid] = mx; ss[tid] = sum; sq[tid] = ssq; __syncthreads();
  for (int o = 128; o; o >>= 1){
    if (tid < o){ sm[tid] = fmaxf(sm[tid], sm[tid+o]); ss[tid] += ss[tid+o]; sq[tid] += sq[tid+o]; }
    __syncthreads();
  }
  float M = sm[0];
  float mean = ss[0] * (1.f/VV);
  float sig = sqrtf(fmaxf(sq[0]*(1.f/VV) - mean*mean, 0.f));
  float thr = M - (0.06f*sig + 0.012f*fabsf(M) + 1e-5f);
  __syncthreads();
  for (int i = tid; i < VV; i += 256){
    if (__bfloat162float(row[i]) >= thr){
      int p = atomicAdd(&ccnt, 1);
      if (p < 64) cand[p] = i;
    }
  }
  __syncthreads();
  int nc = min(ccnt, 64);
  for (int ci = 0; ci < nc; ++ci){
    const float* w = Wv + (size_t)cand[ci]*EMBD;
    float s = dsh[tid]*w[tid] + dsh[tid+256]*w[tid+256];
    sm[tid] = s; __syncthreads();
    for (int o = 128; o; o >>= 1){ if (tid < o) sm[tid] += sm[tid+o]; __syncthreads(); }
    if (tid == 0){ ull p = packmax(sm[0], cand[ci]); if (p > bestsh) bestsh = p; }
    __syncthreads();
  }
  unsigned int low = (unsigned int)(bestsh & 0xFFFFFFFFull);
  int sym = 0x7FFFFFFF - (int)low;
  g_prev[(size_t)b*EMBD + tid]       = emb[(size_t)sym*EMBD + tid];
  g_prev[(size_t)b*EMBD + tid + 256] = emb[(size_t)sym*EMBD + tid + 256];
}

// ---------------- dec history -> 2 bf16 planes ----------------
__global__ void k_asplit(){
  int i = blockIdx.x*blockDim.x + threadIdx.x;   // 1638400
  float x = g_dech[i];
  __nv_bfloat16 b0 = __float2bfloat16(x); float r1 = x - __bfloat162float(b0);
  __nv_bfloat16 b1 = __float2bfloat16(r1);
  g_ah0[i] = b0; g_ah1[i] = b1;
}

// ---------------- batched logits: all (t,b) rows x Wv, 2-plane compensated ----------------
// buffer: A 128 rows x 80 = 10240; B 512 rows x 80 = 40960; buf 51200 x2
#define VBOFF2 10240
#define VBUF2 51200
#define VSMEM2 (2*VBUF2 + 256)

__global__ void __launch_bounds__(256) k_vbig(float* __restrict__ out){
  extern __shared__ __align__(128) char smem[];
  uint32_t sb = smem_u32(smem);
  int tid = threadIdx.x, wid = tid >> 5, lane = tid & 31;
  int n0 = blockIdx.x * 256;
  int wm = wid >> 2, wn = wid & 3;

  int lm  = lane & 15;
  int kbA = ((lane >> 4) & 1) * 16;
  int ln  = (lane & 7) | ((lane >> 1) & 8);
  int kbB = ((lane >> 3) & 1) * 16;
  int r4 = lane >> 2, c2 = (lane & 3)*2;

  for (int mt = 0; mt < TT; ++mt){
    float acc[2][8][4];
#pragma unroll
    for (int mi = 0; mi < 2; ++mi)
#pragma unroll
      for (int ni = 0; ni < 8; ++ni)
#pragma unroll
        for (int e = 0; e < 4; ++e) acc[mi][ni][e] = 0.f;

    auto issue = [&](int c){
      uint32_t bb = sb + (uint32_t)(c & 1)*VBUF2;
      int kc = c*32;
#pragma unroll
      for (int it = 0; it < 10; ++it){
        int i = it*256 + tid;
        if (i < 512){
          int row = i >> 2, g = i & 3;
          int p = row >> 6, m = row & 63;
          const __nv_bfloat16* src = (p ? g_ah1 : g_ah0) + (size_t)(mt*64 + m)*EMBD + kc + g*8;
          cpa16(bb + (uint32_t)row*80 + g*16, src);
        } else {
          int j = i - 512, row = j >> 2, g = j & 3;
          int pb = row >> 8, n = row & 255;
          const __nv_bfloat16* src = (pb ? g_w1 : g_w0) + (size_t)(n0 + n)*EMBD + kc + g*8;
          cpa16(bb + VBOFF2 + (uint32_t)row*80 + g*16, src);
        }
      }
      CP_COMMIT();
    };

    issue(0);
    for (int c = 0; c < 16; ++c){
      if (c + 1 < 16){ issue(c + 1); CP_WAIT(1); } else { CP_WAIT(0); }
      __syncthreads();
      uint32_t bb = sb + (uint32_t)(c & 1)*VBUF2;
#pragma unroll
      for (int kk = 0; kk < 2; ++kk){
        uint32_t aF[2][2][4];
#pragma unroll
        for (int p = 0; p < 2; ++p)
#pragma unroll
          for (int mi = 0; mi < 2; ++mi)
            ldsm4(aF[p][mi], bb + (uint32_t)(p*64 + wm*32 + mi*16 + lm)*80 + kk*32 + kbA);
#pragma unroll
        for (int pb = 0; pb < 2; ++pb){
          uint32_t bF[8][2];
#pragma unroll
          for (int g = 0; g < 4; ++g){
            uint32_t r[4];
            ldsm4(r, bb + VBOFF2 + (uint32_t)(pb*256 + wn*64 + g*16 + ln)*80 + kk*32 + kbB);
            bF[2*g][0] = r[0]; bF[2*g][1] = r[1];
            bF[2*g+1][0] = r[2]; bF[2*g+1][1] = r[3];
          }
          int npa = (pb == 0) ? 2 : 1;   // a0b0, a1b0, a0b1
#pragma unroll
          for (int pa = 0; pa < 2; ++pa){
            if (pa >= npa) break;
#pragma unroll
            for (int mi = 0; mi < 2; ++mi)
#pragma unroll
              for (int ni = 0; ni < 8; ++ni)
                mma16816(acc[mi][ni], aF[pa][mi], bF[ni]);
          }
        }
      }
      __syncthreads();
    }

#pragma unroll
    for (int mi = 0; mi < 2; ++mi)
#pragma unroll
      for (int h = 0; h < 2; ++h){
        int m = wm*32 + mi*16 + r4 + 8*h;   // = batch index b
        float* orow = out + ((size_t)m*TT + mt)*VV + n0 + wn*64;
#pragma unroll
        for (int ni = 0; ni < 8; ++ni)
          __stcs(reinterpret_cast<float2*>(orow + ni*8 + c2),
                 make_float2(acc[mi][ni][2*h], acc[mi][ni][2*h+1]));
      }
  }
}

// ---------------- in-place log-softmax (online logsumexp) ----------------
__global__ void k_lsm(float* __restrict__ out){
  __shared__ float sm[256], ss[256];
  float* p = out + (size_t)blockIdx.x * VV;
  int tid = threadIdx.x;
  float m = -3.4e38f, s = 0.f;
  for (int i = tid; i < VV; i += 256){
    float v = __ldcs(p+i);
    float mn = fmaxf(m, v);
    s = s*expf(m - mn) + expf(v - mn);
    m = mn;
  }
  sm[tid] = m; ss[tid] = s; __syncthreads();
  for (int o = 128; o; o >>= 1){
    if (tid < o){
      float m2 = fmaxf(sm[tid], sm[tid+o]);
      ss[tid] = ss[tid]*expf(sm[tid]-m2) + ss[tid+o]*expf(sm[tid+o]-m2);
      sm[tid] = m2;
    }
    __syncthreads();
  }
  float shift = sm[0] + logf(ss[0]);
  for (int i = tid; i < VV; i += 256) __stcs(p+i, __ldcs(p+i) - shift);
}

__global__ void k_tail(float* __restrict__ out){ out[NPRED + threadIdx.x] = 50.0f; }

extern "C" void kernel_launch(void* const* d_in, const int* in_sizes, int n_in,
                              void* d_out, int out_size){
  const float* ds   = (const float*)d_in[0];
  const float* enc  = (const float*)d_in[1];
  const int*   elen = (const int*)  d_in[2];
  const float* Wih  = (const float*)d_in[4];
  const float* Whh  = (const float*)d_in[5];
  const float* bl   = (const float*)d_in[6];
  const float* Wap  = (const float*)d_in[7];
  const float* Wout = (const float*)d_in[8];
  const float* Wv   = (const float*)d_in[9];
  const float* emb  = (const float*)d_in[10];
  float* out = (float*)d_out;

  cudaFuncSetAttribute(k_vocab1, cudaFuncAttributeMaxDynamicSharedMemorySize, VSMEM1);
  cudaFuncSetAttribute(k_vbig,   cudaFuncAttributeMaxDynamicSharedMemorySize, VSMEM2);

  k_init<<<256,256>>>(ds);
  k_wsplit<<<16000,256>>>(Wv);
  for (int t = 0; t < TT; ++t){
    k_gates<<<dim3(32,4),256>>>(Wih, Whh);
    k_lstm<<<256,256>>>(bl);
    k_q<<<dim3(8,8),256>>>(Wap);
    k_attn<<<64,512>>>(enc, elen);
    k_dec<<<dim3(4,8),256>>>(Wout);
    k_dsplit<<<128,256>>>(t);
    k_vocab1<<<125,256,VSMEM1>>>();
    k_refine<<<64,256>>>(Wv, emb, t);
  }
  k_asplit<<<6400,256>>>();
  k_vbig<<<125,256,VSMEM2>>>(out);
  k_lsm<<<3200,256>>>(out);
  if (out_size >= NPRED + 64) k_tail<<<1,64>>>(out);
}

// round 11
// speedup vs baseline: 1.3853x; 1.0163x over previous
#include <cuda_runtime.h>
#include <cuda_bf16.h>
#include <math.h>
#include <stdint.h>

#define BB 64
#define SS 128
#define HH 1024
#define EE 1024
#define EMBD 512
#define VV 32000
#define TT 50
#define G4 4096
#define NPRED (64*50*32000)

typedef unsigned long long ull;

// ---------------- device scratch (static, no runtime alloc) ----------------
__device__ __align__(16) float g_h[BB*HH];
__device__ __align__(16) float g_c[BB*HH];
__device__ __align__(16) float g_ct[BB*EE];
__device__ __align__(16) float g_gpart[4*BB*G4];
__device__ __align__(16) float g_dpart[8*BB*EMBD];
__device__ __align__(16) float g_dech[(size_t)TT*BB*EMBD];
__device__ __align__(16) float g_keys[(size_t)BB*SS*HH];        // precomputed att keys
__device__ __align__(16) __nv_bfloat16 g_a0[BB*EMBD];
__device__ __align__(16) __nv_bfloat16 g_a1[BB*EMBD];
__device__ __align__(16) __nv_bfloat16 g_ah0[(size_t)TT*BB*EMBD];
__device__ __align__(16) __nv_bfloat16 g_ah1[(size_t)TT*BB*EMBD];
__device__ __align__(16) __nv_bfloat16 g_w0[(size_t)VV*EMBD];
__device__ __align__(16) __nv_bfloat16 g_w1[(size_t)VV*EMBD];
__device__ __align__(16) __nv_bfloat16 g_l1[(size_t)BB*VV];
// exact 3-plane splits for trajectory-critical HMMA
__device__ __align__(16) __nv_bfloat16 g_h0[BB*HH], g_h1[BB*HH], g_h2[BB*HH];
__device__ __align__(16) __nv_bfloat16 g_p0[BB*EMBD], g_p1[BB*EMBD], g_p2[BB*EMBD];
__device__ __align__(16) __nv_bfloat16 g_gw0[(size_t)G4*1536], g_gw1[(size_t)G4*1536], g_gw2[(size_t)G4*1536];
__device__ __align__(16) __nv_bfloat16 g_e0[(size_t)BB*SS*EE], g_e1[(size_t)BB*SS*EE], g_e2[(size_t)BB*SS*EE];
__device__ __align__(16) __nv_bfloat16 g_ap0[(size_t)HH*EE], g_ap1[(size_t)HH*EE], g_ap2[(size_t)HH*EE];

// ---------------- generic helpers ----------------
__device__ __forceinline__ float sigmoidf_(float x){ return 1.f/(1.f+expf(-x)); }
__device__ __forceinline__ ull packmax(float v, int n){
  unsigned int b = __float_as_uint(v);
  b = (b & 0x80000000u) ? ~b : (b | 0x80000000u);
  return ((ull)b << 32) | (unsigned int)(0x7FFFFFFF - n);
}
__device__ __forceinline__ void ffma2(ull &d, ull a, ull b){
  asm("fma.rn.f32x2 %0, %1, %2, %0;" : "+l"(d) : "l"(a), "l"(b));
}
__device__ __forceinline__ ull pk2(float x){
  ull r; asm("mov.b64 %0, {%1, %1};" : "=l"(r) : "f"(x)); return r;
}
__device__ __forceinline__ float2 unpk(ull v){
  float2 r; asm("mov.b64 {%0, %1}, %2;" : "=f"(r.x), "=f"(r.y) : "l"(v)); return r;
}
__device__ __forceinline__ uint32_t smem_u32(const void* p){
  uint32_t a; asm("{ .reg .u64 t; cvta.to.shared.u64 t, %1; cvt.u32.u64 %0, t; }" : "=r"(a) : "l"(p));
  return a;
}
__device__ __forceinline__ void mma16816(float c[4], const uint32_t a[4], const uint32_t b[2]){
  asm volatile("mma.sync.aligned.m16n8k16.row.col.f32.bf16.bf16.f32 "
    "{%0,%1,%2,%3}, {%4,%5,%6,%7}, {%8,%9}, {%0,%1,%2,%3};"
    : "+f"(c[0]), "+f"(c[1]), "+f"(c[2]), "+f"(c[3])
    : "r"(a[0]), "r"(a[1]), "r"(a[2]), "r"(a[3]), "r"(b[0]), "r"(b[1]));
}
__device__ __forceinline__ void ldsm4(uint32_t r[4], uint32_t addr){
  asm volatile("ldmatrix.sync.aligned.m8n8.x4.shared.b16 {%0,%1,%2,%3}, [%4];"
    : "=r"(r[0]), "=r"(r[1]), "=r"(r[2]), "=r"(r[3]) : "r"(addr));
}
__device__ __forceinline__ void cpa16(uint32_t dst, const void* src){
  asm volatile("cp.async.cg.shared.global [%0], [%1], 16;" :: "r"(dst), "l"(src));
}
#define CP_COMMIT() asm volatile("cp.async.commit_group;" ::: "memory")
#define CP_WAIT(n)  asm volatile("cp.async.wait_group %0;" :: "n"(n) : "memory")

__device__ __forceinline__ void split3(float x, __nv_bfloat16 &b0, __nv_bfloat16 &b1, __nv_bfloat16 &b2){
  b0 = __float2bfloat16(x); float r1 = x - __bfloat162float(b0);
  b1 = __float2bfloat16(r1); float r2 = r1 - __bfloat162float(b1);
  b2 = __float2bfloat16(r2);
}

// ---------------- FFMA2 GEMM machinery (dec only) ----------------
struct ALd {
  const float *s0, *s1; int ld0, ld1, cut, tid; float4 v;
  __device__ __forceinline__ void ldg(int k){
    int r = tid >> 2, q = tid & 3;
    const float* s; int ld, kk;
    if (k < cut){ s = s0; ld = ld0; kk = k; } else { s = s1; ld = ld1; kk = k - cut; }
    v = *reinterpret_cast<const float4*>(s + (size_t)r*ld + kk + 4*q);
  }
  __device__ __forceinline__ void sts(float* As) const {
    int r = tid >> 2, q = tid & 3;
    As[(4*q+0)*68+r] = v.x; As[(4*q+1)*68+r] = v.y;
    As[(4*q+2)*68+r] = v.z; As[(4*q+3)*68+r] = v.w;
  }
};
struct BLdT {
  const float *s0, *s1; int ld0, ld1, cut, tid; float4 v0, v1;
  __device__ __forceinline__ void ldg(int k){
    int n = tid >> 1, q = tid & 1;
    const float* s; int ld, kk;
    if (k < cut){ s = s0; ld = ld0; kk = k; } else { s = s1; ld = ld1; kk = k - cut; }
    const float* p = s + (size_t)n*ld + kk + 8*q;
    v0 = *reinterpret_cast<const float4*>(p);
    v1 = *reinterpret_cast<const float4*>(p+4);
  }
  __device__ __forceinline__ void sts(float* Bs) const {
    int n = tid >> 1, kb = (tid & 1)*8;
    Bs[(kb+0)*132+n]=v0.x; Bs[(kb+1)*132+n]=v0.y; Bs[(kb+2)*132+n]=v0.z; Bs[(kb+3)*132+n]=v0.w;
    Bs[(kb+4)*132+n]=v1.x; Bs[(kb+5)*132+n]=v1.y; Bs[(kb+6)*132+n]=v1.z; Bs[(kb+7)*132+n]=v1.w;
  }
};
template<class AL, class BL>
__device__ __forceinline__ void gemm_run(AL a, BL b, int kbase, int ntiles,
                                         ull accv[4][4], int tx, int ty){
  __shared__ __align__(16) float As[2][16*68];
  __shared__ __align__(16) float Bs[2][16*132];
  a.ldg(kbase); b.ldg(kbase);
  a.sts(As[0]); b.sts(Bs[0]);
  __syncthreads();
  int cur = 0;
  for (int kt = 0; kt < ntiles; ++kt){
    bool more = (kt+1) < ntiles;
    if (more){ a.ldg(kbase + (kt+1)*16); b.ldg(kbase + (kt+1)*16); }
    const float* Ac = As[cur]; const float* Bc = Bs[cur];
#pragma unroll
    for (int kk = 0; kk < 16; ++kk){
      const longlong2* ap = reinterpret_cast<const longlong2*>(&Ac[kk*68 + 8*ty]);
      longlong2 aA = ap[0], aB = ap[1];
      float4 bf = *reinterpret_cast<const float4*>(&Bc[kk*132 + 4*tx]);
      ull av[4] = {(ull)aA.x, (ull)aA.y, (ull)aB.x, (ull)aB.y};
      ull bv[4] = {pk2(bf.x), pk2(bf.y), pk2(bf.z), pk2(bf.w)};
#pragma unroll
      for (int i2 = 0; i2 < 4; ++i2)
#pragma unroll
        for (int j = 0; j < 4; ++j)
          ffma2(accv[i2][j], av[i2], bv[j]);
    }
    if (more){ a.sts(As[cur^1]); b.sts(Bs[cur^1]); __syncthreads(); cur ^= 1; }
  }
}
__device__ __forceinline__ void unpack_acc(const ull accv[4][4], float c[8][4]){
#pragma unroll
  for (int i2 = 0; i2 < 4; ++i2){
    float2 u0 = unpk(accv[i2][0]), u1 = unpk(accv[i2][1]);
    float2 u2 = unpk(accv[i2][2]), u3 = unpk(accv[i2][3]);
    c[2*i2  ][0]=u0.x; c[2*i2  ][1]=u1.x; c[2*i2  ][2]=u2.x; c[2*i2  ][3]=u3.x;
    c[2*i2+1][0]=u0.y; c[2*i2+1][1]=u1.y; c[2*i2+1][2]=u2.y; c[2*i2+1][3]=u3.y;
  }
}

// ---------------- init (h fp32 + exact planes; prev planes = 0) ----------------
__global__ void k_init(const float* __restrict__ ds){
  int idx = blockIdx.x*blockDim.x + threadIdx.x;   // 65536
  float h = ds[idx];
  g_h[idx] = h;
  g_c[idx] = ds[65536 + idx];
  split3(h, g_h0[idx], g_h1[idx], g_h2[idx]);
  if (idx < BB*EMBD){
    __nv_bfloat16 z = __float2bfloat16(0.f);
    g_p0[idx] = z; g_p1[idx] = z; g_p2[idx] = z;
  }
}

// ---------------- one-time weight/input splits ----------------
__global__ void k_wsplit(const float* __restrict__ Wv){
  size_t i = ((size_t)blockIdx.x*blockDim.x + threadIdx.x)*4;
  float4 w = *reinterpret_cast<const float4*>(Wv + i);
  float wv[4] = {w.x, w.y, w.z, w.w};
#pragma unroll
  for (int j = 0; j < 4; ++j){
    __nv_bfloat16 b0 = __float2bfloat16(wv[j]); float r1 = wv[j] - __bfloat162float(b0);
    g_w0[i+j] = b0; g_w1[i+j] = __float2bfloat16(r1);
  }
}
// combined gates weight [Wih | Whh] -> 3 planes, row-major [4096 x 1536]
__global__ void k_gwsplit(const float* __restrict__ Wih, const float* __restrict__ Whh){
  size_t i = ((size_t)blockIdx.x*blockDim.x + threadIdx.x)*4;   // over 4096*1536
  size_t n = i / 1536, k = i % 1536;
#pragma unroll
  for (int j = 0; j < 4; ++j){
    size_t kk = k + j;
    float x = (kk < 512) ? Wih[n*512 + kk] : Whh[n*1024 + kk - 512];
    split3(x, g_gw0[i+j], g_gw1[i+j], g_gw2[i+j]);
  }
}
__global__ void k_apsplit(const float* __restrict__ Wap){
  size_t i = ((size_t)blockIdx.x*blockDim.x + threadIdx.x)*4;
#pragma unroll
  for (int j = 0; j < 4; ++j) split3(Wap[i+j], g_ap0[i+j], g_ap1[i+j], g_ap2[i+j]);
}
__global__ void k_esplit(const float* __restrict__ enc){
  size_t i = ((size_t)blockIdx.x*blockDim.x + threadIdx.x)*4;
#pragma unroll
  for (int j = 0; j < 4; ++j) split3(enc[i+j], g_e0[i+j], g_e1[i+j], g_e2[i+j]);
}

// ---------------- keys = enc @ Wap^T (exact 8-product HMMA), once ----------------
// buffer: A 192 rows x 80B = 15360; B 768 rows x 80B = 61440; total 76800 x2
#define KBOFF 15360
#define KBUF 76800
#define KSMEM (2*KBUF + 256)
__global__ void __launch_bounds__(256) k_keys(){
  extern __shared__ __align__(128) char smem[];
  uint32_t sb = smem_u32(smem);
  int tid = threadIdx.x, wid = tid >> 5, lane = tid & 31;
  int m0 = blockIdx.x * 64;       // row block over 8192 (b*128+s)
  int n0 = blockIdx.y * 256;      // col block over 1024 (h)
  int wm = wid >> 2, wn = wid & 3;
  const __nv_bfloat16* a_pl[3] = {g_e0, g_e1, g_e2};
  const __nv_bfloat16* b_pl[3] = {g_ap0, g_ap1, g_ap2};

  float acc[2][8][4];
#pragma unroll
  for (int mi = 0; mi < 2; ++mi)
#pragma unroll
    for (int ni = 0; ni < 8; ++ni)
#pragma unroll
      for (int e = 0; e < 4; ++e) acc[mi][ni][e] = 0.f;

  auto issue = [&](int c){
    uint32_t bb = sb + (uint32_t)(c & 1)*KBUF;
    int kc = c*32;
#pragma unroll
    for (int it = 0; it < 15; ++it){
      int i = it*256 + tid;
      if (i < 768){
        int row = i >> 2, g = i & 3;
        int p = row >> 6, m = row & 63;
        cpa16(bb + (uint32_t)row*80 + g*16, a_pl[p] + (size_t)(m0 + m)*EE + kc + g*8);
      } else {
        int j = i - 768, row = j >> 2, g = j & 3;
        int q = row >> 8, n = row & 255;
        cpa16(bb + KBOFF + (uint32_t)row*80 + g*16, b_pl[q] + (size_t)(n0 + n)*EE + kc + g*8);
      }
    }
    CP_COMMIT();
  };

  int lm  = lane & 15, kbA = ((lane >> 4) & 1)*16;
  int ln  = (lane & 7) | ((lane >> 1) & 8), kbB = ((lane >> 3) & 1)*16;

  issue(0);
  for (int c = 0; c < 32; ++c){
    if (c + 1 < 32){ issue(c + 1); CP_WAIT(1); } else { CP_WAIT(0); }
    __syncthreads();
    uint32_t bb = sb + (uint32_t)(c & 1)*KBUF;
#pragma unroll
    for (int kk = 0; kk < 2; ++kk){
      uint32_t aF[3][2][4];
#pragma unroll
      for (int p = 0; p < 3; ++p)
#pragma unroll
        for (int mi = 0; mi < 2; ++mi)
          ldsm4(aF[p][mi], bb + (uint32_t)(p*64 + wm*32 + mi*16 + lm)*80 + kk*32 + kbA);
#pragma unroll
      for (int q = 0; q < 3; ++q){
        uint32_t bF[8][2];
#pragma unroll
        for (int g = 0; g < 4; ++g){
          uint32_t r[4];
          ldsm4(r, bb + KBOFF + (uint32_t)(q*256 + wn*64 + g*16 + ln)*80 + kk*32 + kbB);
          bF[2*g][0]=r[0]; bF[2*g][1]=r[1]; bF[2*g+1][0]=r[2]; bF[2*g+1][1]=r[3];
        }
#pragma unroll
        for (int p = 0; p < 3; ++p){
          if (p == 2 && q == 2) continue;   // omit a2b2 (~2^-32)
#pragma unroll
          for (int mi = 0; mi < 2; ++mi)
#pragma unroll
            for (int ni = 0; ni < 8; ++ni)
              mma16816(acc[mi][ni], aF[p][mi], bF[ni]);
        }
      }
    }
    __syncthreads();
  }
  int r4 = lane >> 2, c2 = (lane & 3)*2;
#pragma unroll
  for (int mi = 0; mi < 2; ++mi)
#pragma unroll
    for (int h = 0; h < 2; ++h){
      int m = m0 + wm*32 + mi*16 + r4 + 8*h;
      float* orow = g_keys + (size_t)m*HH + n0 + wn*64;
#pragma unroll
      for (int ni = 0; ni < 8; ++ni)
        *reinterpret_cast<float2*>(orow + ni*8 + c2) =
          make_float2(acc[mi][ni][2*h], acc[mi][ni][2*h+1]);
    }
}

// ---------------- gates via exact 8-product HMMA, split-K 4 ----------------
// buffer: A 192 rows x 80 = 15360; B 384 rows x 80 = 30720; total 46080 x2
#define GBOFF 15360
#define GBUF 46080
#define GSMEM (2*GBUF + 256)
__global__ void __launch_bounds__(256) k_gates(){
  extern __shared__ __align__(128) char smem[];
  uint32_t sb = smem_u32(smem);
  int tid = threadIdx.x, wid = tid >> 5, lane = tid & 31;
  int n0 = blockIdx.x * 128;      // over 4096
  int part = blockIdx.y;          // 0..3, K-part of 384
  int wm = wid >> 2, wn = wid & 3;
  const __nv_bfloat16* hp[3] = {g_h0, g_h1, g_h2};
  const __nv_bfloat16* pp[3] = {g_p0, g_p1, g_p2};
  const __nv_bfloat16* wp[3] = {g_gw0, g_gw1, g_gw2};

  float acc[2][4][4];
#pragma unroll
  for (int mi = 0; mi < 2; ++mi)
#pragma unroll
    for (int ni = 0; ni < 4; ++ni)
#pragma unroll
      for (int e = 0; e < 4; ++e) acc[mi][ni][e] = 0.f;

  auto issue = [&](int c){
    uint32_t bb = sb + (uint32_t)(c & 1)*GBUF;
    int kc = part*384 + c*32;
#pragma unroll
    for (int it = 0; it < 9; ++it){
      int i = it*256 + tid;
      if (i < 768){
        int row = i >> 2, g = i & 3;
        int p = row >> 6, m = row & 63;
        const __nv_bfloat16* src = (kc < 512)
          ? pp[p] + (size_t)m*EMBD + kc + g*8
          : hp[p] + (size_t)m*HH + (kc - 512) + g*8;
        cpa16(bb + (uint32_t)row*80 + g*16, src);
      } else {
        int j = i - 768, row = j >> 2, g = j & 3;
        int q = row >> 7, n = row & 127;
        cpa16(bb + GBOFF + (uint32_t)row*80 + g*16,
              wp[q] + (size_t)(n0 + n)*1536 + kc + g*8);
      }
    }
    CP_COMMIT();
  };

  int lm  = lane & 15, kbA = ((lane >> 4) & 1)*16;
  int ln  = (lane & 7) | ((lane >> 1) & 8), kbB = ((lane >> 3) & 1)*16;

  issue(0);
  for (int c = 0; c < 12; ++c){
    if (c + 1 < 12){ issue(c + 1); CP_WAIT(1); } else { CP_WAIT(0); }
    __syncthreads();
    uint32_t bb = sb + (uint32_t)(c & 1)*GBUF;
#pragma unroll
    for (int kk = 0; kk < 2; ++kk){
      uint32_t aF[3][2][4];
#pragma unroll
      for (int p = 0; p < 3; ++p)
#pragma unroll
        for (int mi = 0; mi < 2; ++mi)
          ldsm4(aF[p][mi], bb + (uint32_t)(p*64 + wm*32 + mi*16 + lm)*80 + kk*32 + kbA);
#pragma unroll
      for (int q = 0; q < 3; ++q){
        uint32_t bF[4][2];
#pragma unroll
        for (int g = 0; g < 2; ++g){
          uint32_t r[4];
          ldsm4(r, bb + GBOFF + (uint32_t)(q*128 + wn*32 + g*16 + ln)*80 + kk*32 + kbB);
          bF[2*g][0]=r[0]; bF[2*g][1]=r[1]; bF[2*g+1][0]=r[2]; bF[2*g+1][1]=r[3];
        }
#pragma unroll
        for (int p = 0; p < 3; ++p){
          if (p == 2 && q == 2) continue;
#pragma unroll
          for (int mi = 0; mi < 2; ++mi)
#pragma unroll
            for (int ni = 0; ni < 4; ++ni)
              mma16816(acc[mi][ni], aF[p][mi], bF[ni]);
        }
      }
    }
    __syncthreads();
  }
  int r4 = lane >> 2, c2 = (lane & 3)*2;
  float* o = g_gpart + (size_t)part*BB*G4;
#pragma unroll
  for (int mi = 0; mi < 2; ++mi)
#pragma unroll
    for (int h = 0; h < 2; ++h){
      int m = wm*32 + mi*16 + r4 + 8*h;
#pragma unroll
      for (int ni = 0; ni < 4; ++ni)
        *reinterpret_cast<float2*>(o + (size_t)m*G4 + n0 + wn*32 + ni*8 + c2) =
          make_float2(acc[mi][ni][2*h], acc[mi][ni][2*h+1]);
    }
}

// ---------------- LSTM elementwise + h plane split ----------------
__global__ void k_lstm(const float* __restrict__ bl){
  int idx = blockIdx.x*blockDim.x + threadIdx.x;
  int m = idx >> 10, j = idx & 1023;
  float gi = bl[j], gf = bl[1024+j], gg = bl[2048+j], go = bl[3072+j];
#pragma unroll
  for (int p = 0; p < 4; ++p){
    const float* gp = g_gpart + (size_t)p*BB*G4 + (size_t)m*G4 + j;
    gi += gp[0]; gf += gp[1024]; gg += gp[2048]; go += gp[3072];
  }
  float c = g_c[idx];
  float cn = sigmoidf_(gf)*c + sigmoidf_(gi)*tanhf(gg);
  g_c[idx] = cn;
  float hn = sigmoidf_(go)*tanhf(cn);
  g_h[idx] = hn;
  split3(hn, g_h0[idx], g_h1[idx], g_h2[idx]);
}

// ---------------- fused attention (keys-based) ----------------
__global__ void k_attn(const float* __restrict__ enc, const int* __restrict__ enc_len){
  __shared__ __align__(16) float qv[1024];
  __shared__ float sc[128];
  __shared__ float sr[128];
  int tid = threadIdx.x, b = blockIdx.x;
  for (int e = tid; e < 1024; e += 512) qv[e] = g_h[(size_t)b*HH + e];
  __syncthreads();
  const float* kb = g_keys + (size_t)b*SS*HH;
  const float* eb = enc + (size_t)b*SS*EE;
  const float4* qv4 = reinterpret_cast<const float4*>(qv);
  int w = tid >> 5, lane = tid & 31;
  for (int s = w; s < 128; s += 16){
    const float4* kr4 = reinterpret_cast<const float4*>(kb + (size_t)s*HH);
    float acc = 0.f;
#pragma unroll
    for (int e4 = 0; e4 < 8; ++e4){
      float4 ev = kr4[lane + 32*e4], qvv = qv4[lane + 32*e4];
      acc = fmaf(ev.x, qvv.x, acc); acc = fmaf(ev.y, qvv.y, acc);
      acc = fmaf(ev.z, qvv.z, acc); acc = fmaf(ev.w, qvv.w, acc);
    }
#pragma unroll
    for (int o = 16; o; o >>= 1) acc += __shfl_xor_sync(0xffffffffu, acc, o);
    if (lane == 0) sc[s] = acc;
  }
  __syncthreads();
  int len = enc_len[b];
  bool act = tid < 128;
  float v = -1e9f;
  if (act){ v = (tid < len) ? sc[tid] : -1e9f; sr[tid] = v; }
  __syncthreads();
  for (int o = 64; o; o >>= 1){ if (tid < o) sr[tid] = fmaxf(sr[tid], sr[tid+o]); __syncthreads(); }
  float mx = sr[0]; __syncthreads();
  float ev = 0.f;
  if (act){ ev = expf(v - mx); sr[tid] = ev; }
  __syncthreads();
  for (int o = 64; o; o >>= 1){ if (tid < o) sr[tid] += sr[tid+o]; __syncthreads(); }
  float inv = 1.f / sr[0];
  __syncthreads();
  if (act) sc[tid] = ev * inv;
  __syncthreads();
  float2 a01 = make_float2(0.f, 0.f);
  const float2* eb2 = reinterpret_cast<const float2*>(eb);
  for (int s = 0; s < 128; ++s){
    float al = sc[s];
    float2 e2 = eb2[(size_t)s*512 + tid];
    a01.x = fmaf(al, e2.x, a01.x); a01.y = fmaf(al, e2.y, a01.y);
  }
  reinterpret_cast<float2*>(g_ct + (size_t)b*EE)[tid] = a01;
}

// ---------------- dec = [h | c_t] @ W_out^T (fp32 FFMA2, split-K 8) ----------------
__global__ void __launch_bounds__(256) k_dec(const float* __restrict__ Wout){
  int tid = threadIdx.x, tx = tid & 31, ty = tid >> 5;
  int n0 = blockIdx.x*128, part = blockIdx.y;
  ull accv[4][4] = {};
  ALd  a{g_h, g_ct, 1024, 1024, 1024, tid, {}};
  BLdT b{Wout + (size_t)n0*2048, Wout + (size_t)n0*2048, 2048, 2048, 1<<30, tid, {}, {}};
  gemm_run(a, b, part*256, 16, accv, tx, ty);
  float c[8][4]; unpack_acc(accv, c);
  float* o = g_dpart + (size_t)part*BB*EMBD;
#pragma unroll
  for (int i = 0; i < 8; ++i)
    *reinterpret_cast<float4*>(o + (size_t)(8*ty+i)*EMBD + n0 + 4*tx) =
      make_float4(c[i][0], c[i][1], c[i][2], c[i][3]);
}

// ---------------- sum dec parts -> history + 2 bf16 planes ----------------
__global__ void k_dsplit(int t){
  int i = blockIdx.x*blockDim.x + threadIdx.x;   // 32768
  float s = 0.f;
#pragma unroll
  for (int p = 0; p < 8; ++p) s += g_dpart[p*BB*EMBD + i];
  g_dech[(size_t)t*BB*EMBD + i] = s;
  __nv_bfloat16 a0 = __float2bfloat16(s); float r1 = s - __bfloat162float(a0);
  g_a0[i] = a0; g_a1[i] = __float2bfloat16(r1);
}

// ---------------- in-loop approx vocab: (a0+a1) x b0 -> bf16 scratch ----------------
#define VBOFF1 10240
#define VBUF1 30720
#define VSMEM1 (2*VBUF1 + 256)
__global__ void __launch_bounds__(256) k_vocab1(){
  extern __shared__ __align__(128) char smem[];
  uint32_t sb = smem_u32(smem);
  int tid = threadIdx.x, wid = tid >> 5, lane = tid & 31;
  int n0 = blockIdx.x * 256;
  int wm = wid >> 2, wn = wid & 3;

  float acc[2][8][4];
#pragma unroll
  for (int mi = 0; mi < 2; ++mi)
#pragma unroll
    for (int ni = 0; ni < 8; ++ni)
#pragma unroll
      for (int e = 0; e < 4; ++e) acc[mi][ni][e] = 0.f;

  auto issue = [&](int c){
    uint32_t bb = sb + (uint32_t)(c & 1)*VBUF1;
    int kc = c*32;
#pragma unroll
    for (int it = 0; it < 6; ++it){
      int i = it*256 + tid;
      if (i < 512){
        int row = i >> 2, g = i & 3;
        int p = row >> 6, m = row & 63;
        const __nv_bfloat16* src = (p ? g_a1 : g_a0) + (size_t)m*EMBD + kc + g*8;
        cpa16(bb + (uint32_t)row*80 + g*16, src);
      } else {
        int j = i - 512, row = j >> 2, g = j & 3;
        cpa16(bb + VBOFF1 + (uint32_t)row*80 + g*16,
              g_w0 + (size_t)(n0 + row)*EMBD + kc + g*8);
      }
    }
    CP_COMMIT();
  };

  int lm  = lane & 15, kbA = ((lane >> 4) & 1)*16;
  int ln  = (lane & 7) | ((lane >> 1) & 8), kbB = ((lane >> 3) & 1)*16;

  issue(0);
  for (int c = 0; c < 16; ++c){
    if (c + 1 < 16){ issue(c + 1); CP_WAIT(1); } else { CP_WAIT(0); }
    __syncthreads();
    uint32_t bb = sb + (uint32_t)(c & 1)*VBUF1;
#pragma unroll
    for (int kk = 0; kk < 2; ++kk){
      uint32_t aF[2][2][4];
#pragma unroll
      for (int p = 0; p < 2; ++p)
#pragma unroll
        for (int mi = 0; mi < 2; ++mi)
          ldsm4(aF[p][mi], bb + (uint32_t)(p*64 + wm*32 + mi*16 + lm)*80 + kk*32 + kbA);
      uint32_t bF[8][2];
#pragma unroll
      for (int g = 0; g < 4; ++g){
        uint32_t r[4];
        ldsm4(r, bb + VBOFF1 + (uint32_t)(wn*64 + g*16 + ln)*80 + kk*32 + kbB);
        bF[2*g][0]=r[0]; bF[2*g][1]=r[1]; bF[2*g+1][0]=r[2]; bF[2*g+1][1]=r[3];
      }
#pragma unroll
      for (int pa = 0; pa < 2; ++pa)
#pragma unroll
        for (int mi = 0; mi < 2; ++mi)
#pragma unroll
          for (int ni = 0; ni < 8; ++ni)
            mma16816(acc[mi][ni], aF[pa][mi], bF[ni]);
    }
    __syncthreads();
  }

  int r4 = lane >> 2, c2 = (lane & 3)*2;
#pragma unroll
  for (int mi = 0; mi < 2; ++mi)
#pragma unroll
    for (int h = 0; h < 2; ++h){
      int m = wm*32 + mi*16 + r4 + 8*h;
      __nv_bfloat16* orow = g_l1 + (size_t)m*VV + n0 + wn*64;
#pragma unroll
      for (int ni = 0; ni < 8; ++ni){
        __nv_bfloat162 y = __floats2bfloat162_rn(acc[mi][ni][2*h], acc[mi][ni][2*h+1]);
        *reinterpret_cast<__nv_bfloat162*>(orow + ni*8 + c2) = y;
      }
    }
}

// ---------------- candidate refine + exact argmax + prev plane update ----------------
__global__ void k_refine(const float* __restrict__ Wv, const float* __restrict__ emb, int t){
  __shared__ float sm[256], ss[256], sq[256];
  __shared__ float dsh[512];
  __shared__ int cand[64];
  __shared__ int ccnt;
  __shared__ ull bestsh;
  int b = blockIdx.x, tid = threadIdx.x;
  const __nv_bfloat16* row = g_l1 + (size_t)b*VV;
  const float* dsrc = g_dech + (size_t)t*BB*EMBD + (size_t)b*EMBD;
  dsh[tid] = dsrc[tid]; dsh[tid+256] = dsrc[tid+256];
  if (tid == 0){ ccnt = 0; bestsh = 0ull; }
  float mx = -3.4e38f, sum = 0.f, ssq = 0.f;
  for (int i = tid; i < VV; i += 256){
    float v = __bfloat162float(row[i]);
    mx = fmaxf(mx, v); sum += v; ssq = fmaf(v, v, ssq);
  }
  sm[tid] = mx; ss[tid] = sum; sq[tid] = ssq; __syncthreads();
  for (int o = 128; o; o >>= 1){
    if (tid < o){ sm[tid] = fmaxf(sm[tid], sm[tid+o]); ss[tid] += ss[tid+o]; sq[tid] += sq[tid+o]; }
    __syncthreads();
  }
  float M = sm[0];
  float mean = ss[0] * (1.f/VV);
  float sig = sqrtf(fmaxf(sq[0]*(1.f/VV) - mean*mean, 0.f));
  float thr = M - (0.06f*sig + 0.012f*fabsf(M) + 1e-5f);
  __syncthreads();
  for (int i = tid; i < VV; i += 256){
    if (__bfloat162float(row[i]) >= thr){
      int p = atomicAdd(&ccnt, 1);
      if (p < 64) cand[p] = i;
    }
  }
  __syncthreads();
  int nc = min(ccnt, 64);
  for (int ci = 0; ci < nc; ++ci){
    const float* w = Wv + (size_t)cand[ci]*EMBD;
    float s = dsh[tid]*w[tid] + dsh[tid+256]*w[tid+256];
    sm[tid] = s; __syncthreads();
    for (int o = 128; o; o >>= 1){ if (tid < o) sm[tid] += sm[tid+o]; __syncthreads(); }
    if (tid == 0){ ull p = packmax(sm[0], cand[ci]); if (p > bestsh) bestsh = p; }
    __syncthreads();
  }
  unsigned int low = (unsigned int)(bestsh & 0xFFFFFFFFull);
  int sym = 0x7FFFFFFF - (int)low;
#pragma unroll
  for (int half = 0; half < 2; ++half){
    int i = tid + half*256;
    float e = emb[(size_t)sym*EMBD + i];
    split3(e, g_p0[(size_t)b*EMBD + i], g_p1[(size_t)b*EMBD + i], g_p2[(size_t)b*EMBD + i]);
  }
}

// ---------------- dec history -> 2 bf16 planes ----------------
__global__ void k_asplit(){
  int i = blockIdx.x*blockDim.x + threadIdx.x;
  float x = g_dech[i];
  __nv_bfloat16 b0 = __float2bfloat16(x); float r1 = x - __bfloat162float(b0);
  g_ah0[i] = b0; g_ah1[i] = __float2bfloat16(r1);
}

// ---------------- batched logits ----------------
#define VBOFF2 10240
#define VBUF2 51200
#define VSMEM2 (2*VBUF2 + 256)
__global__ void __launch_bounds__(256) k_vbig(float* __restrict__ out){
  extern __shared__ __align__(128) char smem[];
  uint32_t sb = smem_u32(smem);
  int tid = threadIdx.x, wid = tid >> 5, lane = tid & 31;
  int n0 = blockIdx.x * 256;
  int wm = wid >> 2, wn = wid & 3;

  int lm  = lane & 15, kbA = ((lane >> 4) & 1)*16;
  int ln  = (lane & 7) | ((lane >> 1) & 8), kbB = ((lane >> 3) & 1)*16;
  int r4 = lane >> 2, c2 = (lane & 3)*2;

  for (int mt = 0; mt < TT; ++mt){
    float acc[2][8][4];
#pragma unroll
    for (int mi = 0; mi < 2; ++mi)
#pragma unroll
      for (int ni = 0; ni < 8; ++ni)
#pragma unroll
        for (int e = 0; e < 4; ++e) acc[mi][ni][e] = 0.f;

    auto issue = [&](int c){
      uint32_t bb = sb + (uint32_t)(c & 1)*VBUF2;
      int kc = c*32;
#pragma unroll
      for (int it = 0; it < 10; ++it){
        int i = it*256 + tid;
        if (i < 512){
          int row = i >> 2, g = i & 3;
          int p = row >> 6, m = row & 63;
          const __nv_bfloat16* src = (p ? g_ah1 : g_ah0) + (size_t)(mt*64 + m)*EMBD + kc + g*8;
          cpa16(bb + (uint32_t)row*80 + g*16, src);
        } else {
          int j = i - 512, row = j >> 2, g = j & 3;
          int pb = row >> 8, n = row & 255;
          const __nv_bfloat16* src = (pb ? g_w1 : g_w0) + (size_t)(n0 + n)*EMBD + kc + g*8;
          cpa16(bb + VBOFF2 + (uint32_t)row*80 + g*16, src);
        }
      }
      CP_COMMIT();
    };

    issue(0);
    for (int c = 0; c < 16; ++c){
      if (c + 1 < 16){ issue(c + 1); CP_WAIT(1); } else { CP_WAIT(0); }
      __syncthreads();
      uint32_t bb = sb + (uint32_t)(c & 1)*VBUF2;
#pragma unroll
      for (int kk = 0; kk < 2; ++kk){
        uint32_t aF[2][2][4];
#pragma unroll
        for (int p = 0; p < 2; ++p)
#pragma unroll
          for (int mi = 0; mi < 2; ++mi)
            ldsm4(aF[p][mi], bb + (uint32_t)(p*64 + wm*32 + mi*16 + lm)*80 + kk*32 + kbA);
#pragma unroll
        for (int pb = 0; pb < 2; ++pb){
          uint32_t bF[8][2];
#pragma unroll
          for (int g = 0; g < 4; ++g){
            uint32_t r[4];
            ldsm4(r, bb + VBOFF2 + (uint32_t)(pb*256 + wn*64 + g*16 + ln)*80 + kk*32 + kbB);
            bF[2*g][0]=r[0]; bF[2*g][1]=r[1]; bF[2*g+1][0]=r[2]; bF[2*g+1][1]=r[3];
          }
          int npa = (pb == 0) ? 2 : 1;
#pragma unroll
          for (int pa = 0; pa < 2; ++pa){
            if (pa >= npa) break;
#pragma unroll
            for (int mi = 0; mi < 2; ++mi)
#pragma unroll
              for (int ni = 0; ni < 8; ++ni)
                mma16816(acc[mi][ni], aF[pa][mi], bF[ni]);
          }
        }
      }
      __syncthreads();
    }

#pragma unroll
    for (int mi = 0; mi < 2; ++mi)
#pragma unroll
      for (int h = 0; h < 2; ++h){
        int m = wm*32 + mi*16 + r4 + 8*h;
        float* orow = out + ((size_t)m*TT + mt)*VV + n0 + wn*64;
#pragma unroll
        for (int ni = 0; ni < 8; ++ni)
          __stcs(reinterpret_cast<float2*>(orow + ni*8 + c2),
                 make_float2(acc[mi][ni][2*h], acc[mi][ni][2*h+1]));
      }
  }
}

// ---------------- in-place log-softmax (online logsumexp) ----------------
__global__ void k_lsm(float* __restrict__ out){
  __shared__ float sm[256], ss[256];
  float* p = out + (size_t)blockIdx.x * VV;
  int tid = threadIdx.x;
  float m = -3.4e38f, s = 0.f;
  for (int i = tid; i < VV; i += 256){
    float v = __ldcs(p+i);
    float mn = fmaxf(m, v);
    s = s*expf(m - mn) + expf(v - mn);
    m = mn;
  }
  sm[tid] = m; ss[tid] = s; __syncthreads();
  for (int o = 128; o; o >>= 1){
    if (tid < o){
      float m2 = fmaxf(sm[tid], sm[tid+o]);
      ss[tid] = ss[tid]*expf(sm[tid]-m2) + ss[tid+o]*expf(sm[tid+o]-m2);
      sm[tid] = m2;
    }
    __syncthreads();
  }
  float shift = sm[0] + logf(ss[0]);
  for (int i = tid; i < VV; i += 256) __stcs(p+i, __ldcs(p+i) - shift);
}

__global__ void k_tail(float* __restrict__ out){ out[NPRED + threadIdx.x] = 50.0f; }

extern "C" void kernel_launch(void* const* d_in, const int* in_sizes, int n_in,
                              void* d_out, int out_size){
  const float* ds   = (const float*)d_in[0];
  const float* enc  = (const float*)d_in[1];
  const int*   elen = (const int*)  d_in[2];
  const float* Wih  = (const float*)d_in[4];
  const float* Whh  = (const float*)d_in[5];
  const float* bl   = (const float*)d_in[6];
  const float* Wap  = (const float*)d_in[7];
  const float* Wout = (const float*)d_in[8];
  const float* Wv   = (const float*)d_in[9];
  const float* emb  = (const float*)d_in[10];
  float* out = (float*)d_out;

  cudaFuncSetAttribute(k_vocab1, cudaFuncAttributeMaxDynamicSharedMemorySize, VSMEM1);
  cudaFuncSetAttribute(k_vbig,   cudaFuncAttributeMaxDynamicSharedMemorySize, VSMEM2);
  cudaFuncSetAttribute(k_gates,  cudaFuncAttributeMaxDynamicSharedMemorySize, GSMEM);
  cudaFuncSetAttribute(k_keys,   cudaFuncAttributeMaxDynamicSharedMemorySize, KSMEM);

  k_init<<<256,256>>>(ds);
  k_wsplit<<<16000,256>>>(Wv);
  k_gwsplit<<<6144,256>>>(Wih, Whh);
  k_apsplit<<<1024,256>>>(Wap);
  k_esplit<<<8192,256>>>(enc);
  k_keys<<<dim3(128,4),256,KSMEM>>>();
  for (int t = 0; t < TT; ++t){
    k_gates<<<dim3(32,4),256,GSMEM>>>();
    k_lstm<<<256,256>>>(bl);
    k_attn<<<64,512>>>(enc, elen);
    k_dec<<<dim3(4,8),256>>>(Wout);
    k_dsplit<<<128,256>>>(t);
    k_vocab1<<<125,256,VSMEM1>>>();
    k_refine<<<64,256>>>(Wv, emb, t);
  }
  k_asplit<<<6400,256>>>();
  k_vbig<<<125,256,VSMEM2>>>(out);
  k_lsm<<<3200,256>>>(out);
  if (out_size >= NPRED + 64) k_tail<<<1,64>>>(out);
}